// round 1
// baseline (speedup 1.0000x reference)
#include <cuda_runtime.h>
#include <math.h>

#define BDIM 8
#define NDIM 1024
#define DMODEL 512
#define HH 8
#define DKH 64
#define ST 128
#define MROWS (BDIM * NDIM)
#define KSTRIDE 68

// Scratch (device globals; no allocation in kernel_launch)
__device__ float g_q[MROWS * DMODEL];
__device__ float g_k[MROWS * DMODEL];
__device__ float g_v[MROWS * DMODEL];
__device__ float g_ctx[MROWS * DMODEL];
__device__ float g_y[MROWS * DMODEL];

// ---------------------------------------------------------------------------
// C[m][n] = sum_k A[m][k] * W[n][k] (+ bias[n]) (+ resid[m][n])
// BM=BN=128, BK=16, 256 threads, 8x8 micro-tile per thread.
// M,N multiples of 128; K multiple of 16. No bounds checks.
// ---------------------------------------------------------------------------
__global__ __launch_bounds__(256, 2) void gemm_nt(
    const float* __restrict__ A, const float* __restrict__ W,
    const float* __restrict__ bias, const float* __restrict__ resid,
    float* __restrict__ C, int M, int N, int K)
{
    __shared__ float As[16 * 132];
    __shared__ float Ws[16 * 132];
    const int tid = threadIdx.x;
    const int tx = tid & 15, ty = tid >> 4;
    const int m0 = blockIdx.y * 128, n0 = blockIdx.x * 128;

    float acc[8][8];
#pragma unroll
    for (int i = 0; i < 8; i++)
#pragma unroll
        for (int j = 0; j < 8; j++) acc[i][j] = 0.f;

    for (int k0 = 0; k0 < K; k0 += 16) {
#pragma unroll
        for (int l = 0; l < 2; l++) {
            int idx = tid + l * 256;          // 0..511 float4 slots
            int row = idx >> 2, kc = idx & 3; // row 0..127, kc 0..3
            float4 va = *(const float4*)(A + (size_t)(m0 + row) * K + k0 + kc * 4);
            As[(kc * 4 + 0) * 132 + row] = va.x;
            As[(kc * 4 + 1) * 132 + row] = va.y;
            As[(kc * 4 + 2) * 132 + row] = va.z;
            As[(kc * 4 + 3) * 132 + row] = va.w;
            float4 vw = *(const float4*)(W + (size_t)(n0 + row) * K + k0 + kc * 4);
            Ws[(kc * 4 + 0) * 132 + row] = vw.x;
            Ws[(kc * 4 + 1) * 132 + row] = vw.y;
            Ws[(kc * 4 + 2) * 132 + row] = vw.z;
            Ws[(kc * 4 + 3) * 132 + row] = vw.w;
        }
        __syncthreads();
#pragma unroll
        for (int kk = 0; kk < 16; kk++) {
            float a[8], bb[8];
            *(float4*)&a[0]  = *(float4*)&As[kk * 132 + ty * 4];
            *(float4*)&a[4]  = *(float4*)&As[kk * 132 + 64 + ty * 4];
            *(float4*)&bb[0] = *(float4*)&Ws[kk * 132 + tx * 4];
            *(float4*)&bb[4] = *(float4*)&Ws[kk * 132 + 64 + tx * 4];
#pragma unroll
            for (int i = 0; i < 8; i++)
#pragma unroll
                for (int j = 0; j < 8; j++)
                    acc[i][j] = fmaf(a[i], bb[j], acc[i][j]);
        }
        __syncthreads();
    }

#pragma unroll
    for (int i = 0; i < 8; i++) {
        int m = m0 + ((i < 4) ? (ty * 4 + i) : (64 + ty * 4 + i - 4));
#pragma unroll
        for (int jh = 0; jh < 2; jh++) {
            int n = n0 + jh * 64 + tx * 4;
            float4 c;
            c.x = acc[i][jh * 4 + 0];
            c.y = acc[i][jh * 4 + 1];
            c.z = acc[i][jh * 4 + 2];
            c.w = acc[i][jh * 4 + 3];
            if (bias) {
                float4 b4 = *(const float4*)(bias + n);
                c.x += b4.x; c.y += b4.y; c.z += b4.z; c.w += b4.w;
            }
            if (resid) {
                float4 r4 = *(const float4*)(resid + (size_t)m * N + n);
                c.x += r4.x; c.y += r4.y; c.z += r4.z; c.w += r4.w;
            }
            *(float4*)(C + (size_t)m * N + n) = c;
        }
    }
}

// ---------------------------------------------------------------------------
// Star attention. One block per (b, h, 128-query chunk).
// Stations K/V for (b,h) live in shared memory; loop over 128 queries.
// scores = (q.k + rpe) / 8 over 128 stations (+ self when i >= ST), softmax,
// then ctx = attn @ V.
// ---------------------------------------------------------------------------
__global__ __launch_bounds__(128) void attn_kernel(
    const float* __restrict__ q, const float* __restrict__ k,
    const float* __restrict__ v, const float* __restrict__ rpe,
    float* __restrict__ ctx)
{
    extern __shared__ float sm[];
    float* Ks   = sm;                    // [128][KSTRIDE]
    float* Vs   = Ks + ST * KSTRIDE;     // [128][KSTRIDE]
    float* qs   = Vs + ST * KSTRIDE;     // [64]
    float* sc   = qs + DKH;              // [128]
    float* red4 = sc + ST;               // [4]
    float* redS = red4 + 4;              // [4]
    float* red2 = redS + 4;              // [2]
    float* part = red2 + 2;              // [128]

    const int t = threadIdx.x;
    const int qc = blockIdx.x, h = blockIdx.y, b = blockIdx.z;
    const int lane = t & 31, wid = t >> 5;

    // Load station K/V rows (j = t)
    {
        const float* krow = k + ((size_t)(b * NDIM + t)) * DMODEL + h * DKH;
        const float* vrow = v + ((size_t)(b * NDIM + t)) * DMODEL + h * DKH;
#pragma unroll
        for (int d = 0; d < DKH; d += 4) {
            float4 kv = *(const float4*)(krow + d);
            Ks[t * KSTRIDE + d + 0] = kv.x;
            Ks[t * KSTRIDE + d + 1] = kv.y;
            Ks[t * KSTRIDE + d + 2] = kv.z;
            Ks[t * KSTRIDE + d + 3] = kv.w;
            float4 vv = *(const float4*)(vrow + d);
            Vs[t * KSTRIDE + d + 0] = vv.x;
            Vs[t * KSTRIDE + d + 1] = vv.y;
            Vs[t * KSTRIDE + d + 2] = vv.z;
            Vs[t * KSTRIDE + d + 3] = vv.w;
        }
    }
    const float* rpe_bh = rpe + ((size_t)(b * HH + h)) * NDIM * NDIM;

    const int iend = qc * 128 + 128;
    for (int i = qc * 128; i < iend; i++) {
        __syncthreads();  // protect qs/red reuse from previous iteration
        if (t < 16) {
            float4 qv = *(const float4*)(q + ((size_t)(b * NDIM + i)) * DMODEL + h * DKH + t * 4);
            *(float4*)&qs[t * 4] = qv;
        }
        __syncthreads();

        const bool has_self = (i >= ST);

        // score for station j = t
        float s = rpe_bh[(size_t)i * NDIM + t];
        {
            const float* kr = Ks + t * KSTRIDE;
#pragma unroll
            for (int d = 0; d < DKH; d += 4) {
                float4 q4 = *(const float4*)&qs[d];
                float4 k4 = *(const float4*)&kr[d];
                s = fmaf(q4.x, k4.x, s);
                s = fmaf(q4.y, k4.y, s);
                s = fmaf(q4.z, k4.z, s);
                s = fmaf(q4.w, k4.w, s);
            }
            s *= 0.125f;
        }

        // self-score dot (threads 0..63 over two warps)
        if (has_self && t < DKH) {
            float p = qs[t] * k[((size_t)(b * NDIM + i)) * DMODEL + h * DKH + t];
#pragma unroll
            for (int off = 16; off > 0; off >>= 1)
                p += __shfl_down_sync(0xffffffffu, p, off);
            if (lane == 0) red2[wid] = p;
        }

        // warp max of s
        float mw = s;
#pragma unroll
        for (int off = 16; off > 0; off >>= 1)
            mw = fmaxf(mw, __shfl_xor_sync(0xffffffffu, mw, off));
        if (lane == 0) red4[wid] = mw;
        __syncthreads();

        float s_self = -3.0e38f;
        if (has_self)
            s_self = (red2[0] + red2[1] + rpe_bh[(size_t)i * NDIM + i]) * 0.125f;
        float m = fmaxf(fmaxf(red4[0], red4[1]), fmaxf(red4[2], red4[3]));
        m = fmaxf(m, s_self);

        float p = __expf(s - m);
        sc[t] = p;
        float sw = p;
#pragma unroll
        for (int off = 16; off > 0; off >>= 1)
            sw += __shfl_xor_sync(0xffffffffu, sw, off);
        if (lane == 0) redS[wid] = sw;
        __syncthreads();

        const float p_self = has_self ? __expf(s_self - m) : 0.f;
        const float Z = redS[0] + redS[1] + redS[2] + redS[3] + p_self;

        // ctx partial: thread handles dim d over half the stations
        {
            const int d = t & 63, half = t >> 6;
            const float* vb = Vs + half * 64 * KSTRIDE + d;
            const float* pb = sc + half * 64;
            float acc = 0.f;
#pragma unroll 8
            for (int j = 0; j < 64; j++)
                acc = fmaf(pb[j], vb[j * KSTRIDE], acc);
            part[half * 64 + d] = acc;
        }
        __syncthreads();

        if (t < DKH) {
            float val = part[t] + part[64 + t];
            if (has_self)
                val += p_self * v[((size_t)(b * NDIM + i)) * DMODEL + h * DKH + t];
            ctx[((size_t)(b * NDIM + i)) * DMODEL + h * DKH + t] = val / Z;
        }
    }
}

// ---------------------------------------------------------------------------
// LayerNorm over rows of 512. One block per row.
// ---------------------------------------------------------------------------
__global__ __launch_bounds__(128) void ln_kernel(
    const float* __restrict__ y, const float* __restrict__ g,
    const float* __restrict__ bta, float* __restrict__ out)
{
    __shared__ float sh1[4], sh2[4];
    const int row = blockIdx.x, t = threadIdx.x;
    const int lane = t & 31, wid = t >> 5;

    float4 vv = *(const float4*)(y + (size_t)row * DMODEL + t * 4);
    float s  = vv.x + vv.y + vv.z + vv.w;
    float s2 = vv.x * vv.x + vv.y * vv.y + vv.z * vv.z + vv.w * vv.w;
#pragma unroll
    for (int off = 16; off > 0; off >>= 1) {
        s  += __shfl_xor_sync(0xffffffffu, s, off);
        s2 += __shfl_xor_sync(0xffffffffu, s2, off);
    }
    if (lane == 0) { sh1[wid] = s; sh2[wid] = s2; }
    __syncthreads();
    float tot  = sh1[0] + sh1[1] + sh1[2] + sh1[3];
    float tot2 = sh2[0] + sh2[1] + sh2[2] + sh2[3];
    float mu  = tot * (1.f / 512.f);
    float var = tot2 * (1.f / 512.f) - mu * mu;
    float rs  = rsqrtf(var + 1e-6f);

    float4 gg = *(const float4*)(g + t * 4);
    float4 bb = *(const float4*)(bta + t * 4);
    float4 o;
    o.x = (vv.x - mu) * rs * gg.x + bb.x;
    o.y = (vv.y - mu) * rs * gg.y + bb.y;
    o.z = (vv.z - mu) * rs * gg.z + bb.z;
    o.w = (vv.w - mu) * rs * gg.w + bb.w;
    *(float4*)(out + (size_t)row * DMODEL + t * 4) = o;
}

// ---------------------------------------------------------------------------
extern "C" void kernel_launch(void* const* d_in, const int* in_sizes, int n_in,
                              void* d_out, int out_size)
{
    const float* hidden = (const float*)d_in[0];
    const float* rpe    = (const float*)d_in[1];
    const float* Wq     = (const float*)d_in[2];
    const float* Wk     = (const float*)d_in[3];
    const float* Wv     = (const float*)d_in[4];
    const float* fcw    = (const float*)d_in[5];
    const float* fcb    = (const float*)d_in[6];
    const float* lng    = (const float*)d_in[7];
    const float* lnb    = (const float*)d_in[8];
    float* out = (float*)d_out;

    float *qb, *kb, *vb, *ctxb, *yb;
    cudaGetSymbolAddress((void**)&qb, g_q);
    cudaGetSymbolAddress((void**)&kb, g_k);
    cudaGetSymbolAddress((void**)&vb, g_v);
    cudaGetSymbolAddress((void**)&ctxb, g_ctx);
    cudaGetSymbolAddress((void**)&yb, g_y);

    dim3 gg(DMODEL / 128, MROWS / 128);
    gemm_nt<<<gg, 256>>>(hidden, Wq, nullptr, nullptr, qb, MROWS, DMODEL, DMODEL);
    gemm_nt<<<gg, 256>>>(hidden, Wk, nullptr, nullptr, kb, MROWS, DMODEL, DMODEL);
    gemm_nt<<<gg, 256>>>(hidden, Wv, nullptr, nullptr, vb, MROWS, DMODEL, DMODEL);

    const int smem = (2 * ST * KSTRIDE + DKH + ST + 4 + 4 + 2 + 128) * (int)sizeof(float);
    cudaFuncSetAttribute(attn_kernel, cudaFuncAttributeMaxDynamicSharedMemorySize, smem);
    attn_kernel<<<dim3(NDIM / 128, HH, BDIM), 128, smem>>>(qb, kb, vb, rpe, ctxb);

    gemm_nt<<<gg, 256>>>(ctxb, fcw, fcb, hidden, yb, MROWS, DMODEL, DMODEL);
    ln_kernel<<<MROWS, 128>>>(yb, lng, lnb, out);
}

// round 3
// speedup vs baseline: 2.0492x; 2.0492x over previous
#include <cuda_runtime.h>
#include <math.h>

#define BDIM 8
#define NDIM 1024
#define DMODEL 512
#define HH 8
#define DKH 64
#define ST 128
#define MROWS (BDIM * NDIM)

// Scratch (device globals; no allocation in kernel_launch)
__device__ float g_q[MROWS * DMODEL];
__device__ float g_k[MROWS * DMODEL];
__device__ float g_v[MROWS * DMODEL];
__device__ float g_ctx[MROWS * DMODEL];
__device__ float g_y[MROWS * DMODEL];

// ---------------------------------------------------------------------------
// C[m][n] = sum_k A[m][k] * W[n][k] (+ bias[n]) (+ resid[m][n])
// BM=BN=128, BK=16, 256 threads, 8x8 micro-tile per thread.
// ---------------------------------------------------------------------------
__global__ __launch_bounds__(256, 2) void gemm_nt(
    const float* __restrict__ A, const float* __restrict__ W,
    const float* __restrict__ bias, const float* __restrict__ resid,
    float* __restrict__ C, int M, int N, int K)
{
    __shared__ float As[16 * 132];
    __shared__ float Ws[16 * 132];
    const int tid = threadIdx.x;
    const int tx = tid & 15, ty = tid >> 4;
    const int m0 = blockIdx.y * 128, n0 = blockIdx.x * 128;

    float acc[8][8];
#pragma unroll
    for (int i = 0; i < 8; i++)
#pragma unroll
        for (int j = 0; j < 8; j++) acc[i][j] = 0.f;

    for (int k0 = 0; k0 < K; k0 += 16) {
#pragma unroll
        for (int l = 0; l < 2; l++) {
            int idx = tid + l * 256;
            int row = idx >> 2, kc = idx & 3;
            float4 va = *(const float4*)(A + (size_t)(m0 + row) * K + k0 + kc * 4);
            As[(kc * 4 + 0) * 132 + row] = va.x;
            As[(kc * 4 + 1) * 132 + row] = va.y;
            As[(kc * 4 + 2) * 132 + row] = va.z;
            As[(kc * 4 + 3) * 132 + row] = va.w;
            float4 vw = *(const float4*)(W + (size_t)(n0 + row) * K + k0 + kc * 4);
            Ws[(kc * 4 + 0) * 132 + row] = vw.x;
            Ws[(kc * 4 + 1) * 132 + row] = vw.y;
            Ws[(kc * 4 + 2) * 132 + row] = vw.z;
            Ws[(kc * 4 + 3) * 132 + row] = vw.w;
        }
        __syncthreads();
#pragma unroll
        for (int kk = 0; kk < 16; kk++) {
            float a[8], bb[8];
            *(float4*)&a[0]  = *(float4*)&As[kk * 132 + ty * 4];
            *(float4*)&a[4]  = *(float4*)&As[kk * 132 + 64 + ty * 4];
            *(float4*)&bb[0] = *(float4*)&Ws[kk * 132 + tx * 4];
            *(float4*)&bb[4] = *(float4*)&Ws[kk * 132 + 64 + tx * 4];
#pragma unroll
            for (int i = 0; i < 8; i++)
#pragma unroll
                for (int j = 0; j < 8; j++)
                    acc[i][j] = fmaf(a[i], bb[j], acc[i][j]);
        }
        __syncthreads();
    }

#pragma unroll
    for (int i = 0; i < 8; i++) {
        int m = m0 + ((i < 4) ? (ty * 4 + i) : (64 + ty * 4 + i - 4));
#pragma unroll
        for (int jh = 0; jh < 2; jh++) {
            int n = n0 + jh * 64 + tx * 4;
            float4 c;
            c.x = acc[i][jh * 4 + 0];
            c.y = acc[i][jh * 4 + 1];
            c.z = acc[i][jh * 4 + 2];
            c.w = acc[i][jh * 4 + 3];
            if (bias) {
                float4 b4 = *(const float4*)(bias + n);
                c.x += b4.x; c.y += b4.y; c.z += b4.z; c.w += b4.w;
            }
            if (resid) {
                float4 r4 = *(const float4*)(resid + (size_t)m * N + n);
                c.x += r4.x; c.y += r4.y; c.z += r4.z; c.w += r4.w;
            }
            *(float4*)(C + (size_t)m * N + n) = c;
        }
    }
}

// ---------------------------------------------------------------------------
// Star attention, chunked-GEMM formulation.
// One CTA per (b, h, 128-query chunk). 256 threads.
//   Phase 1: S[128x128] = Q_chunk[128x64] . K_stations^T, init from RPE, *0.125
//   Phase 2: row softmax over 128 stations (+ self column if chunk > 0)
//   Phase 3: ctx[128x64] = P . V_stations (+ p_self * v_self), / Z
// ---------------------------------------------------------------------------
#define QS_STR 132
#define S_STR  132
#define V_STR  68

__global__ __launch_bounds__(256, 1) void attn_kernel(
    const float* __restrict__ q, const float* __restrict__ k,
    const float* __restrict__ v, const float* __restrict__ rpe,
    float* __restrict__ ctx)
{
    extern __shared__ float sm[];
    float* Qs = sm;                      // [64][QS_STR]  transposed: Qs[d][i]
    float* Ks = Qs + DKH * QS_STR;       // [64][QS_STR]  transposed: Ks[d][j]
    float* Vs = Ks + DKH * QS_STR;       // [128][V_STR]  Vs[j][d]
    float* S  = Vs + ST * V_STR;         // [128][S_STR]
    float* Zr = S + 128 * S_STR;         // [128]
    float* Ps = Zr + 128;                // [128] p_self

    const int tid = threadIdx.x;
    const int tx = tid & 15, ty = tid >> 4;
    const int qc = blockIdx.x, h = blockIdx.y, b = blockIdx.z;
    const int i0 = qc * 128;
    const bool has_self = (qc > 0);
    const int lane = tid & 31, wid = tid >> 5;

    const float* rpe_bh = rpe + ((size_t)(b * HH + h)) * NDIM * NDIM;

    // ---- load Q (transposed), K stations (transposed), V stations ----
#pragma unroll
    for (int l = 0; l < 8; l++) {
        int idx = tid + l * 256;             // 0..2047 float4 slots
        int row = idx >> 4, c = idx & 15;    // row 0..127, c 0..15
        float4 va = *(const float4*)(q + ((size_t)(b * NDIM + i0 + row)) * DMODEL + h * DKH + c * 4);
        Qs[(c * 4 + 0) * QS_STR + row] = va.x;
        Qs[(c * 4 + 1) * QS_STR + row] = va.y;
        Qs[(c * 4 + 2) * QS_STR + row] = va.z;
        Qs[(c * 4 + 3) * QS_STR + row] = va.w;
        float4 vk = *(const float4*)(k + ((size_t)(b * NDIM + row)) * DMODEL + h * DKH + c * 4);
        Ks[(c * 4 + 0) * QS_STR + row] = vk.x;
        Ks[(c * 4 + 1) * QS_STR + row] = vk.y;
        Ks[(c * 4 + 2) * QS_STR + row] = vk.z;
        Ks[(c * 4 + 3) * QS_STR + row] = vk.w;
        float4 vv = *(const float4*)(v + ((size_t)(b * NDIM + row)) * DMODEL + h * DKH + c * 4);
        *(float4*)(Vs + row * V_STR + c * 4) = vv;
    }
    __syncthreads();

    // ---- Phase 1: S = Q.K^T (8x8 microtile per thread) ----
    {
        float acc[8][8];
#pragma unroll
        for (int i = 0; i < 8; i++)
#pragma unroll
            for (int j = 0; j < 8; j++) acc[i][j] = 0.f;

#pragma unroll 8
        for (int kk = 0; kk < DKH; kk++) {
            float a[8], bb[8];
            *(float4*)&a[0]  = *(float4*)&Qs[kk * QS_STR + ty * 4];
            *(float4*)&a[4]  = *(float4*)&Qs[kk * QS_STR + 64 + ty * 4];
            *(float4*)&bb[0] = *(float4*)&Ks[kk * QS_STR + tx * 4];
            *(float4*)&bb[4] = *(float4*)&Ks[kk * QS_STR + 64 + tx * 4];
#pragma unroll
            for (int i = 0; i < 8; i++)
#pragma unroll
                for (int j = 0; j < 8; j++)
                    acc[i][j] = fmaf(a[i], bb[j], acc[i][j]);
        }
        // write S with RPE add + scale
#pragma unroll
        for (int i = 0; i < 8; i++) {
            int m = (i < 4) ? (ty * 4 + i) : (64 + ty * 4 + i - 4);
#pragma unroll
            for (int jh = 0; jh < 2; jh++) {
                int n = jh * 64 + tx * 4;
                float4 r4 = *(const float4*)(rpe_bh + (size_t)(i0 + m) * NDIM + n);
                float4 c;
                c.x = (acc[i][jh * 4 + 0] + r4.x) * 0.125f;
                c.y = (acc[i][jh * 4 + 1] + r4.y) * 0.125f;
                c.z = (acc[i][jh * 4 + 2] + r4.z) * 0.125f;
                c.w = (acc[i][jh * 4 + 3] + r4.w) * 0.125f;
                *(float4*)(S + m * S_STR + n) = c;
            }
        }
    }
    __syncthreads();

    // ---- Phase 2: row softmax (each warp handles 16 rows) ----
    for (int r16 = 0; r16 < 16; r16++) {
        int i = wid * 16 + r16;
        float4 x = *(float4*)(S + i * S_STR + lane * 4);
        float mx = fmaxf(fmaxf(x.x, x.y), fmaxf(x.z, x.w));
#pragma unroll
        for (int off = 16; off > 0; off >>= 1)
            mx = fmaxf(mx, __shfl_xor_sync(0xffffffffu, mx, off));

        float s_self = -3.0e38f;
        if (has_self) {
            // dot(q_i, k_i): lanes cover d = lane, lane+32
            const float* krow = k + ((size_t)(b * NDIM + i0 + i)) * DMODEL + h * DKH;
            float p = Qs[lane * QS_STR + i] * krow[lane]
                    + Qs[(lane + 32) * QS_STR + i] * krow[lane + 32];
#pragma unroll
            for (int off = 16; off > 0; off >>= 1)
                p += __shfl_xor_sync(0xffffffffu, p, off);
            s_self = (p + rpe_bh[(size_t)(i0 + i) * NDIM + (i0 + i)]) * 0.125f;
            mx = fmaxf(mx, s_self);
        }

        float4 e;
        e.x = __expf(x.x - mx);
        e.y = __expf(x.y - mx);
        e.z = __expf(x.z - mx);
        e.w = __expf(x.w - mx);
        *(float4*)(S + i * S_STR + lane * 4) = e;
        float sum = e.x + e.y + e.z + e.w;
#pragma unroll
        for (int off = 16; off > 0; off >>= 1)
            sum += __shfl_xor_sync(0xffffffffu, sum, off);

        float pself = has_self ? __expf(s_self - mx) : 0.f;
        if (lane == 0) {
            Zr[i] = sum + pself;
            Ps[i] = pself;
        }
    }
    __syncthreads();

    // ---- Phase 3: ctx = P.V  (8 rows x 4 cols per thread) ----
    {
        float acc[8][4];
#pragma unroll
        for (int i = 0; i < 8; i++)
#pragma unroll
            for (int j = 0; j < 4; j++) acc[i][j] = 0.f;

        const int ibase = ty * 8;
#pragma unroll 4
        for (int j = 0; j < ST; j++) {
            float4 v4 = *(float4*)(Vs + j * V_STR + tx * 4);
#pragma unroll
            for (int r = 0; r < 8; r++) {
                float p = S[(ibase + r) * S_STR + j];
                acc[r][0] = fmaf(p, v4.x, acc[r][0]);
                acc[r][1] = fmaf(p, v4.y, acc[r][1]);
                acc[r][2] = fmaf(p, v4.z, acc[r][2]);
                acc[r][3] = fmaf(p, v4.w, acc[r][3]);
            }
        }

#pragma unroll
        for (int r = 0; r < 8; r++) {
            int i = ibase + r;
            float invZ = 1.f / Zr[i];
            float4 o;
            o.x = acc[r][0]; o.y = acc[r][1]; o.z = acc[r][2]; o.w = acc[r][3];
            if (has_self) {
                float ps = Ps[i];
                float4 vs = *(const float4*)(v + ((size_t)(b * NDIM + i0 + i)) * DMODEL + h * DKH + tx * 4);
                o.x = fmaf(ps, vs.x, o.x);
                o.y = fmaf(ps, vs.y, o.y);
                o.z = fmaf(ps, vs.z, o.z);
                o.w = fmaf(ps, vs.w, o.w);
            }
            o.x *= invZ; o.y *= invZ; o.z *= invZ; o.w *= invZ;
            *(float4*)(ctx + ((size_t)(b * NDIM + i0 + i)) * DMODEL + h * DKH + tx * 4) = o;
        }
    }
}

// ---------------------------------------------------------------------------
// LayerNorm over rows of 512. One block per row.
// ---------------------------------------------------------------------------
__global__ __launch_bounds__(128) void ln_kernel(
    const float* __restrict__ y, const float* __restrict__ g,
    const float* __restrict__ bta, float* __restrict__ out)
{
    __shared__ float sh1[4], sh2[4];
    const int row = blockIdx.x, t = threadIdx.x;
    const int lane = t & 31, wid = t >> 5;

    float4 vv = *(const float4*)(y + (size_t)row * DMODEL + t * 4);
    float s  = vv.x + vv.y + vv.z + vv.w;
    float s2 = vv.x * vv.x + vv.y * vv.y + vv.z * vv.z + vv.w * vv.w;
#pragma unroll
    for (int off = 16; off > 0; off >>= 1) {
        s  += __shfl_xor_sync(0xffffffffu, s, off);
        s2 += __shfl_xor_sync(0xffffffffu, s2, off);
    }
    if (lane == 0) { sh1[wid] = s; sh2[wid] = s2; }
    __syncthreads();
    float tot  = sh1[0] + sh1[1] + sh1[2] + sh1[3];
    float tot2 = sh2[0] + sh2[1] + sh2[2] + sh2[3];
    float mu  = tot * (1.f / 512.f);
    float var = tot2 * (1.f / 512.f) - mu * mu;
    float rs  = rsqrtf(var + 1e-6f);

    float4 gg = *(const float4*)(g + t * 4);
    float4 bb = *(const float4*)(bta + t * 4);
    float4 o;
    o.x = (vv.x - mu) * rs * gg.x + bb.x;
    o.y = (vv.y - mu) * rs * gg.y + bb.y;
    o.z = (vv.z - mu) * rs * gg.z + bb.z;
    o.w = (vv.w - mu) * rs * gg.w + bb.w;
    *(float4*)(out + (size_t)row * DMODEL + t * 4) = o;
}

// ---------------------------------------------------------------------------
extern "C" void kernel_launch(void* const* d_in, const int* in_sizes, int n_in,
                              void* d_out, int out_size)
{
    const float* hidden = (const float*)d_in[0];
    const float* rpe    = (const float*)d_in[1];
    const float* Wq     = (const float*)d_in[2];
    const float* Wk     = (const float*)d_in[3];
    const float* Wv     = (const float*)d_in[4];
    const float* fcw    = (const float*)d_in[5];
    const float* fcb    = (const float*)d_in[6];
    const float* lng    = (const float*)d_in[7];
    const float* lnb    = (const float*)d_in[8];
    float* out = (float*)d_out;

    float *qb, *kb, *vb, *ctxb, *yb;
    cudaGetSymbolAddress((void**)&qb, g_q);
    cudaGetSymbolAddress((void**)&kb, g_k);
    cudaGetSymbolAddress((void**)&vb, g_v);
    cudaGetSymbolAddress((void**)&ctxb, g_ctx);
    cudaGetSymbolAddress((void**)&yb, g_y);

    dim3 gg(DMODEL / 128, MROWS / 128);
    gemm_nt<<<gg, 256>>>(hidden, Wq, nullptr, nullptr, qb, MROWS, DMODEL, DMODEL);
    gemm_nt<<<gg, 256>>>(hidden, Wk, nullptr, nullptr, kb, MROWS, DMODEL, DMODEL);
    gemm_nt<<<gg, 256>>>(hidden, Wv, nullptr, nullptr, vb, MROWS, DMODEL, DMODEL);

    const int smem = (2 * DKH * QS_STR + ST * V_STR + 128 * S_STR + 256) * (int)sizeof(float);
    static int attr_set = 0;
    if (!attr_set) {
        cudaFuncSetAttribute(attn_kernel, cudaFuncAttributeMaxDynamicSharedMemorySize, smem);
        attr_set = 1;
    }
    attn_kernel<<<dim3(NDIM / 128, HH, BDIM), 256, smem>>>(qb, kb, vb, rpe, ctxb);

    gemm_nt<<<gg, 256>>>(ctxb, fcw, fcb, hidden, yb, MROWS, DMODEL, DMODEL);
    ln_kernel<<<MROWS, 128>>>(yb, lng, lnb, out);
}

// round 8
// speedup vs baseline: 2.3710x; 1.1570x over previous
#include <cuda_runtime.h>
#include <cuda_bf16.h>
#include <cstdint>
#include <math.h>

#define BDIM 8
#define NDIM 1024
#define DMODEL 512
#define HH 8
#define DKH 64
#define ST 128
#define MROWS (BDIM * NDIM)

// ---------------- scratch (device globals) ----------------
__device__ float g_q[MROWS * DMODEL];
__device__ float g_k[MROWS * DMODEL];
__device__ float g_v[MROWS * DMODEL];
__device__ float g_ctx[MROWS * DMODEL];
__device__ float g_y[MROWS * DMODEL];
__device__ __nv_bfloat16 g_ahi[MROWS * DMODEL];
__device__ __nv_bfloat16 g_alo[MROWS * DMODEL];
__device__ __nv_bfloat16 g_chi[MROWS * DMODEL];
__device__ __nv_bfloat16 g_clo[MROWS * DMODEL];
__device__ __nv_bfloat16 g_whi[4 * DMODEL * DMODEL];
__device__ __nv_bfloat16 g_wlo[4 * DMODEL * DMODEL];

__device__ __forceinline__ uint32_t smem_to_u32(const void* smem_ptr) {
    uint32_t addr;
    asm("{ .reg .u64 tmp; cvta.to.shared.u64 tmp, %1; cvt.u32.u64 %0, tmp; }"
        : "=r"(addr) : "l"(smem_ptr));
    return addr;
}

// ---------------------------------------------------------------------------
// split fp32 -> bf16 hi + bf16 lo (residual)
// ---------------------------------------------------------------------------
__global__ __launch_bounds__(256) void split_kernel(
    const float* __restrict__ x, __nv_bfloat16* __restrict__ hi,
    __nv_bfloat16* __restrict__ lo, int n4)
{
    int i = blockIdx.x * 256 + threadIdx.x;
    if (i >= n4) return;
    float4 v = ((const float4*)x)[i];
    union { __nv_bfloat16 b[4]; uint2 u; } H, L;
    H.b[0] = __float2bfloat16(v.x);
    H.b[1] = __float2bfloat16(v.y);
    H.b[2] = __float2bfloat16(v.z);
    H.b[3] = __float2bfloat16(v.w);
    L.b[0] = __float2bfloat16(v.x - __bfloat162float(H.b[0]));
    L.b[1] = __float2bfloat16(v.y - __bfloat162float(H.b[1]));
    L.b[2] = __float2bfloat16(v.z - __bfloat162float(H.b[2]));
    L.b[3] = __float2bfloat16(v.w - __bfloat162float(H.b[3]));
    ((uint2*)hi)[i] = H.u;
    ((uint2*)lo)[i] = L.u;
}

// ---------------------------------------------------------------------------
// HMMA split-bf16 GEMM: C[m][n] = sum_k A[m][k]*W[n][k] (+bias)(+resid)
// Accumulates Ahi*Bhi + Ahi*Blo + Alo*Bhi in fp32 via mma.sync.m16n8k16.
// CTA 128x128, 4 warps (each 64x64), K in 48 chunks of 32 (3 passes x 16),
// cp.async 3-stage pipeline. smem row stride 40 bf16 (80 B, 16B-aligned,
// conflict-free fragment LDS: bases mod 32 cover all banks).
// ---------------------------------------------------------------------------
#define SASTR 40
#define HALF_STAGE 10240            // 128 * 40 * 2 bytes
#define STAGE_BYTES 20480           // A + B tiles

__global__ __launch_bounds__(128) void gemm_tc(
    const __nv_bfloat16* __restrict__ Ahi, const __nv_bfloat16* __restrict__ Alo,
    const __nv_bfloat16* __restrict__ Bhi, const __nv_bfloat16* __restrict__ Blo,
    const float* __restrict__ bias, const float* __restrict__ resid,
    float* __restrict__ C)
{
    extern __shared__ char smem[];
    const uint32_t smem_base = smem_to_u32(smem);
    const int tid = threadIdx.x;
    const int lane = tid & 31, warp = tid >> 5;
    const int n0 = blockIdx.x * 128, m0 = blockIdx.y * 128;
    const int wm0 = (warp >> 1) * 64, wn0 = (warp & 1) * 64;

    float acc[4][8][4];
#pragma unroll
    for (int mt = 0; mt < 4; mt++)
#pragma unroll
        for (int nt = 0; nt < 8; nt++)
#pragma unroll
            for (int c = 0; c < 4; c++) acc[mt][nt][c] = 0.f;

#define ISSUE_LOAD(sidx, Ap, Bp, kk0) do {                                     \
    uint32_t _sa = smem_base + (sidx) * STAGE_BYTES + tid * 80;                \
    uint32_t _sb = _sa + HALF_STAGE;                                           \
    const __nv_bfloat16* _ga = (Ap) + (size_t)(m0 + tid) * DMODEL + (kk0);     \
    const __nv_bfloat16* _gb = (Bp) + (size_t)(n0 + tid) * DMODEL + (kk0);     \
    _Pragma("unroll")                                                          \
    for (int _c = 0; _c < 4; _c++) {                                           \
        asm volatile("cp.async.cg.shared.global [%0], [%1], 16;"               \
                     :: "r"(_sa + _c * 16), "l"(_ga + _c * 8) : "memory");     \
        asm volatile("cp.async.cg.shared.global [%0], [%1], 16;"               \
                     :: "r"(_sb + _c * 16), "l"(_gb + _c * 8) : "memory");     \
    }                                                                          \
} while (0)

    // prologue: chunk 0 (pass 0 = hi,hi; k0 = 0)
    ISSUE_LOAD(0, Ahi, Bhi, 0);
    asm volatile("cp.async.commit_group;" ::: "memory");

    for (int i = 0; i < 48; i++) {
        const int nxt = i + 1;
        if (nxt < 48) {
            const int p = nxt >> 4;
            const int k0 = (nxt & 15) * 32;
            const __nv_bfloat16* Asrc = (p == 2) ? Alo : Ahi;
            const __nv_bfloat16* Bsrc = (p == 1) ? Blo : Bhi;
            ISSUE_LOAD(nxt % 3, Asrc, Bsrc, k0);
        }
        asm volatile("cp.async.commit_group;" ::: "memory");
        asm volatile("cp.async.wait_group 1;" ::: "memory");
        __syncthreads();

        const __nv_bfloat16* As = (const __nv_bfloat16*)(smem + (i % 3) * STAGE_BYTES);
        const __nv_bfloat16* Bs = (const __nv_bfloat16*)((const char*)As + HALF_STAGE);

#pragma unroll
        for (int ks = 0; ks < 2; ks++) {
            uint32_t af[4][4];
            uint32_t bfr[8][2];
#pragma unroll
            for (int mt = 0; mt < 4; mt++) {
                const __nv_bfloat16* p =
                    As + (wm0 + mt * 16 + (lane >> 2)) * SASTR + ks * 16 + (lane & 3) * 2;
                af[mt][0] = *(const uint32_t*)p;
                af[mt][1] = *(const uint32_t*)(p + 8 * SASTR);
                af[mt][2] = *(const uint32_t*)(p + 8);
                af[mt][3] = *(const uint32_t*)(p + 8 * SASTR + 8);
            }
#pragma unroll
            for (int nt = 0; nt < 8; nt++) {
                const __nv_bfloat16* p =
                    Bs + (wn0 + nt * 8 + (lane >> 2)) * SASTR + ks * 16 + (lane & 3) * 2;
                bfr[nt][0] = *(const uint32_t*)p;
                bfr[nt][1] = *(const uint32_t*)(p + 8);
            }
#pragma unroll
            for (int mt = 0; mt < 4; mt++)
#pragma unroll
                for (int nt = 0; nt < 8; nt++) {
                    asm volatile(
                        "mma.sync.aligned.m16n8k16.row.col.f32.bf16.bf16.f32 "
                        "{%0,%1,%2,%3}, {%4,%5,%6,%7}, {%8,%9}, {%0,%1,%2,%3};"
                        : "+f"(acc[mt][nt][0]), "+f"(acc[mt][nt][1]),
                          "+f"(acc[mt][nt][2]), "+f"(acc[mt][nt][3])
                        : "r"(af[mt][0]), "r"(af[mt][1]), "r"(af[mt][2]), "r"(af[mt][3]),
                          "r"(bfr[nt][0]), "r"(bfr[nt][1]));
                }
        }
        __syncthreads();
    }

    // epilogue
#pragma unroll
    for (int mt = 0; mt < 4; mt++) {
        const int r = m0 + wm0 + mt * 16 + (lane >> 2);
#pragma unroll
        for (int nt = 0; nt < 8; nt++) {
            const int cn = n0 + wn0 + nt * 8 + (lane & 3) * 2;
            float2 v0 = make_float2(acc[mt][nt][0], acc[mt][nt][1]);
            float2 v1 = make_float2(acc[mt][nt][2], acc[mt][nt][3]);
            if (bias) {
                float2 b2 = *(const float2*)(bias + cn);
                v0.x += b2.x; v0.y += b2.y;
                v1.x += b2.x; v1.y += b2.y;
            }
            if (resid) {
                float2 r0 = *(const float2*)(resid + (size_t)r * DMODEL + cn);
                float2 r1 = *(const float2*)(resid + (size_t)(r + 8) * DMODEL + cn);
                v0.x += r0.x; v0.y += r0.y;
                v1.x += r1.x; v1.y += r1.y;
            }
            *(float2*)(C + (size_t)r * DMODEL + cn) = v0;
            *(float2*)(C + (size_t)(r + 8) * DMODEL + cn) = v1;
        }
    }
}

// ---------------------------------------------------------------------------
// Star attention (unchanged from passing round-3 version)
// ---------------------------------------------------------------------------
#define QS_STR 132
#define S_STR  132
#define V_STR  68

__global__ __launch_bounds__(256, 1) void attn_kernel(
    const float* __restrict__ q, const float* __restrict__ k,
    const float* __restrict__ v, const float* __restrict__ rpe,
    float* __restrict__ ctx)
{
    extern __shared__ float sm[];
    float* Qs = sm;
    float* Ks = Qs + DKH * QS_STR;
    float* Vs = Ks + DKH * QS_STR;
    float* S  = Vs + ST * V_STR;
    float* Zr = S + 128 * S_STR;
    float* Ps = Zr + 128;

    const int tid = threadIdx.x;
    const int tx = tid & 15, ty = tid >> 4;
    const int qc = blockIdx.x, h = blockIdx.y, b = blockIdx.z;
    const int i0 = qc * 128;
    const bool has_self = (qc > 0);
    const int lane = tid & 31, wid = tid >> 5;

    const float* rpe_bh = rpe + ((size_t)(b * HH + h)) * NDIM * NDIM;

#pragma unroll
    for (int l = 0; l < 8; l++) {
        int idx = tid + l * 256;
        int row = idx >> 4, c = idx & 15;
        float4 va = *(const float4*)(q + ((size_t)(b * NDIM + i0 + row)) * DMODEL + h * DKH + c * 4);
        Qs[(c * 4 + 0) * QS_STR + row] = va.x;
        Qs[(c * 4 + 1) * QS_STR + row] = va.y;
        Qs[(c * 4 + 2) * QS_STR + row] = va.z;
        Qs[(c * 4 + 3) * QS_STR + row] = va.w;
        float4 vk = *(const float4*)(k + ((size_t)(b * NDIM + row)) * DMODEL + h * DKH + c * 4);
        Ks[(c * 4 + 0) * QS_STR + row] = vk.x;
        Ks[(c * 4 + 1) * QS_STR + row] = vk.y;
        Ks[(c * 4 + 2) * QS_STR + row] = vk.z;
        Ks[(c * 4 + 3) * QS_STR + row] = vk.w;
        float4 vv = *(const float4*)(v + ((size_t)(b * NDIM + row)) * DMODEL + h * DKH + c * 4);
        *(float4*)(Vs + row * V_STR + c * 4) = vv;
    }
    __syncthreads();

    {
        float acc[8][8];
#pragma unroll
        for (int i = 0; i < 8; i++)
#pragma unroll
            for (int j = 0; j < 8; j++) acc[i][j] = 0.f;

#pragma unroll 8
        for (int kk = 0; kk < DKH; kk++) {
            float a[8], bb[8];
            *(float4*)&a[0]  = *(float4*)&Qs[kk * QS_STR + ty * 4];
            *(float4*)&a[4]  = *(float4*)&Qs[kk * QS_STR + 64 + ty * 4];
            *(float4*)&bb[0] = *(float4*)&Ks[kk * QS_STR + tx * 4];
            *(float4*)&bb[4] = *(float4*)&Ks[kk * QS_STR + 64 + tx * 4];
#pragma unroll
            for (int i = 0; i < 8; i++)
#pragma unroll
                for (int j = 0; j < 8; j++)
                    acc[i][j] = fmaf(a[i], bb[j], acc[i][j]);
        }
#pragma unroll
        for (int i = 0; i < 8; i++) {
            int m = (i < 4) ? (ty * 4 + i) : (64 + ty * 4 + i - 4);
#pragma unroll
            for (int jh = 0; jh < 2; jh++) {
                int n = jh * 64 + tx * 4;
                float4 r4 = *(const float4*)(rpe_bh + (size_t)(i0 + m) * NDIM + n);
                float4 c;
                c.x = (acc[i][jh * 4 + 0] + r4.x) * 0.125f;
                c.y = (acc[i][jh * 4 + 1] + r4.y) * 0.125f;
                c.z = (acc[i][jh * 4 + 2] + r4.z) * 0.125f;
                c.w = (acc[i][jh * 4 + 3] + r4.w) * 0.125f;
                *(float4*)(S + m * S_STR + n) = c;
            }
        }
    }
    __syncthreads();

    for (int r16 = 0; r16 < 16; r16++) {
        int i = wid * 16 + r16;
        float4 x = *(float4*)(S + i * S_STR + lane * 4);
        float mx = fmaxf(fmaxf(x.x, x.y), fmaxf(x.z, x.w));
#pragma unroll
        for (int off = 16; off > 0; off >>= 1)
            mx = fmaxf(mx, __shfl_xor_sync(0xffffffffu, mx, off));

        float s_self = -3.0e38f;
        if (has_self) {
            const float* krow = k + ((size_t)(b * NDIM + i0 + i)) * DMODEL + h * DKH;
            float p = Qs[lane * QS_STR + i] * krow[lane]
                    + Qs[(lane + 32) * QS_STR + i] * krow[lane + 32];
#pragma unroll
            for (int off = 16; off > 0; off >>= 1)
                p += __shfl_xor_sync(0xffffffffu, p, off);
            s_self = (p + rpe_bh[(size_t)(i0 + i) * NDIM + (i0 + i)]) * 0.125f;
            mx = fmaxf(mx, s_self);
        }

        float4 e;
        e.x = __expf(x.x - mx);
        e.y = __expf(x.y - mx);
        e.z = __expf(x.z - mx);
        e.w = __expf(x.w - mx);
        *(float4*)(S + i * S_STR + lane * 4) = e;
        float sum = e.x + e.y + e.z + e.w;
#pragma unroll
        for (int off = 16; off > 0; off >>= 1)
            sum += __shfl_xor_sync(0xffffffffu, sum, off);

        float pself = has_self ? __expf(s_self - mx) : 0.f;
        if (lane == 0) {
            Zr[i] = sum + pself;
            Ps[i] = pself;
        }
    }
    __syncthreads();

    {
        float acc[8][4];
#pragma unroll
        for (int i = 0; i < 8; i++)
#pragma unroll
            for (int j = 0; j < 4; j++) acc[i][j] = 0.f;

        const int ibase = ty * 8;
#pragma unroll 4
        for (int j = 0; j < ST; j++) {
            float4 v4 = *(float4*)(Vs + j * V_STR + tx * 4);
#pragma unroll
            for (int r = 0; r < 8; r++) {
                float p = S[(ibase + r) * S_STR + j];
                acc[r][0] = fmaf(p, v4.x, acc[r][0]);
                acc[r][1] = fmaf(p, v4.y, acc[r][1]);
                acc[r][2] = fmaf(p, v4.z, acc[r][2]);
                acc[r][3] = fmaf(p, v4.w, acc[r][3]);
            }
        }

#pragma unroll
        for (int r = 0; r < 8; r++) {
            int i = ibase + r;
            float invZ = 1.f / Zr[i];
            float4 o;
            o.x = acc[r][0]; o.y = acc[r][1]; o.z = acc[r][2]; o.w = acc[r][3];
            if (has_self) {
                float ps = Ps[i];
                float4 vs = *(const float4*)(v + ((size_t)(b * NDIM + i0 + i)) * DMODEL + h * DKH + tx * 4);
                o.x = fmaf(ps, vs.x, o.x);
                o.y = fmaf(ps, vs.y, o.y);
                o.z = fmaf(ps, vs.z, o.z);
                o.w = fmaf(ps, vs.w, o.w);
            }
            o.x *= invZ; o.y *= invZ; o.z *= invZ; o.w *= invZ;
            *(float4*)(ctx + ((size_t)(b * NDIM + i0 + i)) * DMODEL + h * DKH + tx * 4) = o;
        }
    }
}

// ---------------------------------------------------------------------------
// LayerNorm over rows of 512.
// ---------------------------------------------------------------------------
__global__ __launch_bounds__(128) void ln_kernel(
    const float* __restrict__ y, const float* __restrict__ g,
    const float* __restrict__ bta, float* __restrict__ out)
{
    __shared__ float sh1[4], sh2[4];
    const int row = blockIdx.x, t = threadIdx.x;
    const int lane = t & 31, wid = t >> 5;

    float4 vv = *(const float4*)(y + (size_t)row * DMODEL + t * 4);
    float s  = vv.x + vv.y + vv.z + vv.w;
    float s2 = vv.x * vv.x + vv.y * vv.y + vv.z * vv.z + vv.w * vv.w;
#pragma unroll
    for (int off = 16; off > 0; off >>= 1) {
        s  += __shfl_xor_sync(0xffffffffu, s, off);
        s2 += __shfl_xor_sync(0xffffffffu, s2, off);
    }
    if (lane == 0) { sh1[wid] = s; sh2[wid] = s2; }
    __syncthreads();
    float tot  = sh1[0] + sh1[1] + sh1[2] + sh1[3];
    float tot2 = sh2[0] + sh2[1] + sh2[2] + sh2[3];
    float mu  = tot * (1.f / 512.f);
    float var = tot2 * (1.f / 512.f) - mu * mu;
    float rs  = rsqrtf(var + 1e-6f);

    float4 gg = *(const float4*)(g + t * 4);
    float4 bb = *(const float4*)(bta + t * 4);
    float4 o;
    o.x = (vv.x - mu) * rs * gg.x + bb.x;
    o.y = (vv.y - mu) * rs * gg.y + bb.y;
    o.z = (vv.z - mu) * rs * gg.z + bb.z;
    o.w = (vv.w - mu) * rs * gg.w + bb.w;
    *(float4*)(out + (size_t)row * DMODEL + t * 4) = o;
}

// ---------------------------------------------------------------------------
extern "C" void kernel_launch(void* const* d_in, const int* in_sizes, int n_in,
                              void* d_out, int out_size)
{
    const float* hidden = (const float*)d_in[0];
    const float* rpe    = (const float*)d_in[1];
    const float* Wq     = (const float*)d_in[2];
    const float* Wk     = (const float*)d_in[3];
    const float* Wv     = (const float*)d_in[4];
    const float* fcw    = (const float*)d_in[5];
    const float* fcb    = (const float*)d_in[6];
    const float* lng    = (const float*)d_in[7];
    const float* lnb    = (const float*)d_in[8];
    float* out = (float*)d_out;

    float *qb, *kb, *vb, *ctxb, *yb;
    __nv_bfloat16 *ahi, *alo, *chi, *clo, *whi, *wlo;
    cudaGetSymbolAddress((void**)&qb, g_q);
    cudaGetSymbolAddress((void**)&kb, g_k);
    cudaGetSymbolAddress((void**)&vb, g_v);
    cudaGetSymbolAddress((void**)&ctxb, g_ctx);
    cudaGetSymbolAddress((void**)&yb, g_y);
    cudaGetSymbolAddress((void**)&ahi, g_ahi);
    cudaGetSymbolAddress((void**)&alo, g_alo);
    cudaGetSymbolAddress((void**)&chi, g_chi);
    cudaGetSymbolAddress((void**)&clo, g_clo);
    cudaGetSymbolAddress((void**)&whi, g_whi);
    cudaGetSymbolAddress((void**)&wlo, g_wlo);

    const int GEMM_SMEM = 3 * STAGE_BYTES;  // 61440
    const int ATTN_SMEM = (2 * DKH * QS_STR + ST * V_STR + 128 * S_STR + 256) * (int)sizeof(float);
    static int attr_set = 0;
    if (!attr_set) {
        cudaFuncSetAttribute(gemm_tc, cudaFuncAttributeMaxDynamicSharedMemorySize, GEMM_SMEM);
        cudaFuncSetAttribute(attn_kernel, cudaFuncAttributeMaxDynamicSharedMemorySize, ATTN_SMEM);
        attr_set = 1;
    }

    const int WSZ = DMODEL * DMODEL;
    const int n4h = MROWS * DMODEL / 4;
    const int n4w = WSZ / 4;

    split_kernel<<<n4h / 256, 256>>>(hidden, ahi, alo, n4h);
    split_kernel<<<n4w / 256, 256>>>(Wq,  whi + 0 * WSZ, wlo + 0 * WSZ, n4w);
    split_kernel<<<n4w / 256, 256>>>(Wk,  whi + 1 * WSZ, wlo + 1 * WSZ, n4w);
    split_kernel<<<n4w / 256, 256>>>(Wv,  whi + 2 * WSZ, wlo + 2 * WSZ, n4w);
    split_kernel<<<n4w / 256, 256>>>(fcw, whi + 3 * WSZ, wlo + 3 * WSZ, n4w);

    dim3 gg(DMODEL / 128, MROWS / 128);
    gemm_tc<<<gg, 128, GEMM_SMEM>>>(ahi, alo, whi + 0 * WSZ, wlo + 0 * WSZ, nullptr, nullptr, qb);
    gemm_tc<<<gg, 128, GEMM_SMEM>>>(ahi, alo, whi + 1 * WSZ, wlo + 1 * WSZ, nullptr, nullptr, kb);
    gemm_tc<<<gg, 128, GEMM_SMEM>>>(ahi, alo, whi + 2 * WSZ, wlo + 2 * WSZ, nullptr, nullptr, vb);

    attn_kernel<<<dim3(NDIM / 128, HH, BDIM), 256, ATTN_SMEM>>>(qb, kb, vb, rpe, ctxb);

    split_kernel<<<n4h / 256, 256>>>(ctxb, chi, clo, n4h);
    gemm_tc<<<gg, 128, GEMM_SMEM>>>(chi, clo, whi + 3 * WSZ, wlo + 3 * WSZ, fcb, hidden, yb);

    ln_kernel<<<MROWS, 128>>>(yb, lng, lnb, out);
}

// round 9
// speedup vs baseline: 2.9787x; 1.2563x over previous
#include <cuda_runtime.h>
#include <cuda_bf16.h>
#include <cstdint>
#include <math.h>

#define BDIM 8
#define NDIM 1024
#define DMODEL 512
#define HH 8
#define DKH 64
#define ST 128
#define MROWS (BDIM * NDIM)
#define WSZ (DMODEL * DMODEL)

// ---------------- scratch (device globals) ----------------
__device__ float g_q[MROWS * DMODEL];
__device__ float g_k[MROWS * DMODEL];
__device__ float g_v[MROWS * DMODEL];
__device__ float g_ctx[MROWS * DMODEL];
__device__ float g_y[MROWS * DMODEL];
__device__ __nv_bfloat16 g_ahi[MROWS * DMODEL];
__device__ __nv_bfloat16 g_alo[MROWS * DMODEL];
__device__ __nv_bfloat16 g_chi[MROWS * DMODEL];
__device__ __nv_bfloat16 g_clo[MROWS * DMODEL];
__device__ __nv_bfloat16 g_whi[4 * WSZ];
__device__ __nv_bfloat16 g_wlo[4 * WSZ];

__device__ __forceinline__ uint32_t smem_to_u32(const void* smem_ptr) {
    uint32_t addr;
    asm("{ .reg .u64 tmp; cvta.to.shared.u64 tmp, %1; cvt.u32.u64 %0, tmp; }"
        : "=r"(addr) : "l"(smem_ptr));
    return addr;
}

#define LDSM_X4(r0, r1, r2, r3, addr)                                          \
    asm volatile("ldmatrix.sync.aligned.m8n8.x4.shared.b16 {%0,%1,%2,%3}, [%4];" \
                 : "=r"(r0), "=r"(r1), "=r"(r2), "=r"(r3) : "r"(addr))

// ---------------------------------------------------------------------------
// split fp32 -> bf16 hi + bf16 lo (residual)
// ---------------------------------------------------------------------------
__global__ __launch_bounds__(256) void split_kernel(
    const float* __restrict__ x, __nv_bfloat16* __restrict__ hi,
    __nv_bfloat16* __restrict__ lo, int n4)
{
    int i = blockIdx.x * 256 + threadIdx.x;
    if (i >= n4) return;
    float4 v = ((const float4*)x)[i];
    union { __nv_bfloat16 b[4]; uint2 u; } H, L;
    H.b[0] = __float2bfloat16(v.x);
    H.b[1] = __float2bfloat16(v.y);
    H.b[2] = __float2bfloat16(v.z);
    H.b[3] = __float2bfloat16(v.w);
    L.b[0] = __float2bfloat16(v.x - __bfloat162float(H.b[0]));
    L.b[1] = __float2bfloat16(v.y - __bfloat162float(H.b[1]));
    L.b[2] = __float2bfloat16(v.z - __bfloat162float(H.b[2]));
    L.b[3] = __float2bfloat16(v.w - __bfloat162float(H.b[3]));
    ((uint2*)hi)[i] = H.u;
    ((uint2*)lo)[i] = L.u;
}

// fused 4-weight split: blockIdx.y selects which weight matrix
__global__ __launch_bounds__(256) void split4_kernel(
    const float* __restrict__ w0, const float* __restrict__ w1,
    const float* __restrict__ w2, const float* __restrict__ w3,
    __nv_bfloat16* __restrict__ hi, __nv_bfloat16* __restrict__ lo)
{
    const int z = blockIdx.y;
    const float* src = (z == 0) ? w0 : (z == 1) ? w1 : (z == 2) ? w2 : w3;
    int i = blockIdx.x * 256 + threadIdx.x;           // 0 .. WSZ/4-1
    float4 v = ((const float4*)src)[i];
    union { __nv_bfloat16 b[4]; uint2 u; } H, L;
    H.b[0] = __float2bfloat16(v.x);
    H.b[1] = __float2bfloat16(v.y);
    H.b[2] = __float2bfloat16(v.z);
    H.b[3] = __float2bfloat16(v.w);
    L.b[0] = __float2bfloat16(v.x - __bfloat162float(H.b[0]));
    L.b[1] = __float2bfloat16(v.y - __bfloat162float(H.b[1]));
    L.b[2] = __float2bfloat16(v.z - __bfloat162float(H.b[2]));
    L.b[3] = __float2bfloat16(v.w - __bfloat162float(H.b[3]));
    ((uint2*)(hi + (size_t)z * WSZ))[i] = H.u;
    ((uint2*)(lo + (size_t)z * WSZ))[i] = L.u;
}

// ---------------------------------------------------------------------------
// HMMA split-bf16 GEMM (ldmatrix + 4-stage cp.async).
// C[m][n] = sum_k A[m][k]*W[n][k] (+bias)(+resid), via
// Ahi*Bhi + Ahi*Blo + Alo*Bhi with fp32 accum (mma.sync.m16n8k16).
// CTA 128x128, 4 warps (64x64 each), 48 chunks of K=32 (3 passes x 16).
// blockIdx.z selects weight slab + output buffer (QKV fusion).
// ---------------------------------------------------------------------------
#define SASTR 40
#define HALF_STAGE 10240            // 128 * 40 * 2 bytes
#define STAGE_BYTES 20480           // A + B tiles
#define GEMM_SMEM (4 * STAGE_BYTES) // 81920

__global__ __launch_bounds__(128) void gemm_tc(
    const __nv_bfloat16* __restrict__ Ahi, const __nv_bfloat16* __restrict__ Alo,
    const __nv_bfloat16* __restrict__ BhiBase, const __nv_bfloat16* __restrict__ BloBase,
    const float* __restrict__ bias, const float* __restrict__ resid,
    float* __restrict__ C0, float* __restrict__ C1, float* __restrict__ C2)
{
    extern __shared__ char smem[];
    const uint32_t smem_base = smem_to_u32(smem);
    const int tid = threadIdx.x;
    const int lane = tid & 31, warp = tid >> 5;
    const int z = blockIdx.z;
    const __nv_bfloat16* Bhi = BhiBase + (size_t)z * WSZ;
    const __nv_bfloat16* Blo = BloBase + (size_t)z * WSZ;
    float* C = (z == 0) ? C0 : (z == 1) ? C1 : C2;
    const int n0 = blockIdx.x * 128, m0 = blockIdx.y * 128;
    const int wm0 = (warp >> 1) * 64, wn0 = (warp & 1) * 64;

    // lane-dependent ldmatrix address components
    const int a_row = wm0 + (lane & 15);
    const int a_coff = (lane >> 4) * 8;
    const int b_row = wn0 + (lane & 7) + ((lane >> 4) << 3);
    const int b_coff = ((lane >> 3) & 1) * 8;

    float acc[4][8][4];
#pragma unroll
    for (int mt = 0; mt < 4; mt++)
#pragma unroll
        for (int nt = 0; nt < 8; nt++)
#pragma unroll
            for (int c = 0; c < 4; c++) acc[mt][nt][c] = 0.f;

#define ISSUE_LOAD(sidx, Ap, Bp, kk0) do {                                     \
    uint32_t _sa = smem_base + (sidx) * STAGE_BYTES + tid * 80;                \
    uint32_t _sb = _sa + HALF_STAGE;                                           \
    const __nv_bfloat16* _ga = (Ap) + (size_t)(m0 + tid) * DMODEL + (kk0);     \
    const __nv_bfloat16* _gb = (Bp) + (size_t)(n0 + tid) * DMODEL + (kk0);     \
    _Pragma("unroll")                                                          \
    for (int _c = 0; _c < 4; _c++) {                                           \
        asm volatile("cp.async.cg.shared.global [%0], [%1], 16;"               \
                     :: "r"(_sa + _c * 16), "l"(_ga + _c * 8) : "memory");     \
        asm volatile("cp.async.cg.shared.global [%0], [%1], 16;"               \
                     :: "r"(_sb + _c * 16), "l"(_gb + _c * 8) : "memory");     \
    }                                                                          \
} while (0)

#define CHUNK_SRC(idx, Ap, Bp, K0) \
    const int _p = (idx) >> 4; const int K0 = ((idx) & 15) * 32;               \
    const __nv_bfloat16* Ap = (_p == 2) ? Alo : Ahi;                           \
    const __nv_bfloat16* Bp = (_p == 1) ? Blo : Bhi;

    // prologue: 3 stages in flight
#pragma unroll
    for (int s = 0; s < 3; s++) {
        CHUNK_SRC(s, Ap, Bp, k0);
        ISSUE_LOAD(s, Ap, Bp, k0);
        asm volatile("cp.async.commit_group;" ::: "memory");
    }

    for (int i = 0; i < 48; i++) {
        asm volatile("cp.async.wait_group 2;" ::: "memory");
        __syncthreads();

        const uint32_t As_b = smem_base + (i & 3) * STAGE_BYTES;
        const uint32_t Bs_b = As_b + HALF_STAGE;

#pragma unroll
        for (int ks = 0; ks < 2; ks++) {
            uint32_t af[4][4];
            uint32_t bfr[8][2];
#pragma unroll
            for (int mt = 0; mt < 4; mt++) {
                uint32_t ad = As_b + (uint32_t)(((a_row + mt * 16) * SASTR) + ks * 16 + a_coff) * 2;
                LDSM_X4(af[mt][0], af[mt][1], af[mt][2], af[mt][3], ad);
            }
#pragma unroll
            for (int np = 0; np < 4; np++) {
                uint32_t bd = Bs_b + (uint32_t)(((b_row + np * 16) * SASTR) + ks * 16 + b_coff) * 2;
                LDSM_X4(bfr[np * 2][0], bfr[np * 2][1], bfr[np * 2 + 1][0], bfr[np * 2 + 1][1], bd);
            }
#pragma unroll
            for (int mt = 0; mt < 4; mt++)
#pragma unroll
                for (int nt = 0; nt < 8; nt++) {
                    asm volatile(
                        "mma.sync.aligned.m16n8k16.row.col.f32.bf16.bf16.f32 "
                        "{%0,%1,%2,%3}, {%4,%5,%6,%7}, {%8,%9}, {%0,%1,%2,%3};"
                        : "+f"(acc[mt][nt][0]), "+f"(acc[mt][nt][1]),
                          "+f"(acc[mt][nt][2]), "+f"(acc[mt][nt][3])
                        : "r"(af[mt][0]), "r"(af[mt][1]), "r"(af[mt][2]), "r"(af[mt][3]),
                          "r"(bfr[nt][0]), "r"(bfr[nt][1]));
                }
        }

        const int nxt = i + 3;
        if (nxt < 48) {
            CHUNK_SRC(nxt, Ap, Bp, k0);
            ISSUE_LOAD((nxt & 3), Ap, Bp, k0);
        }
        asm volatile("cp.async.commit_group;" ::: "memory");
    }

    // epilogue
#pragma unroll
    for (int mt = 0; mt < 4; mt++) {
        const int r = m0 + wm0 + mt * 16 + (lane >> 2);
#pragma unroll
        for (int nt = 0; nt < 8; nt++) {
            const int cn = n0 + wn0 + nt * 8 + (lane & 3) * 2;
            float2 v0 = make_float2(acc[mt][nt][0], acc[mt][nt][1]);
            float2 v1 = make_float2(acc[mt][nt][2], acc[mt][nt][3]);
            if (bias) {
                float2 b2 = *(const float2*)(bias + cn);
                v0.x += b2.x; v0.y += b2.y;
                v1.x += b2.x; v1.y += b2.y;
            }
            if (resid) {
                float2 r0 = *(const float2*)(resid + (size_t)r * DMODEL + cn);
                float2 r1 = *(const float2*)(resid + (size_t)(r + 8) * DMODEL + cn);
                v0.x += r0.x; v0.y += r0.y;
                v1.x += r1.x; v1.y += r1.y;
            }
            *(float2*)(C + (size_t)r * DMODEL + cn) = v0;
            *(float2*)(C + (size_t)(r + 8) * DMODEL + cn) = v1;
        }
    }
}

// ---------------------------------------------------------------------------
// Star attention v2: S aliases Qs/Ks (dead after phase 1 reg-accumulation),
// self-dot precomputed from gmem, smem 104KB -> 2 CTAs/SM.
// ---------------------------------------------------------------------------
#define QS_STR 132
#define S_STR  132
#define V_STR  68
// float offsets
#define OFF_KS (DKH * QS_STR)            // 8448
#define OFF_VS (2 * DKH * QS_STR)        // 16896  (S aliases [0 .. 16896))
#define OFF_SD (OFF_VS + ST * V_STR)     // 25600
#define OFF_ZR (OFF_SD + 128)            // 25728
#define OFF_PS (OFF_ZR + 128)            // 25856
#define ATTN_SMEM ((OFF_PS + 128) * 4)   // 103936 bytes

__global__ __launch_bounds__(256, 2) void attn_kernel(
    const float* __restrict__ q, const float* __restrict__ k,
    const float* __restrict__ v, const float* __restrict__ rpe,
    float* __restrict__ ctx)
{
    extern __shared__ float sm[];
    float* Qs = sm;                 // phase1 only
    float* Ks = sm + OFF_KS;        // phase1 only
    float* S  = sm;                 // phase>=1 write (aliases Qs/Ks)
    float* Vs = sm + OFF_VS;
    float* sd = sm + OFF_SD;
    float* Zr = sm + OFF_ZR;
    float* Ps = sm + OFF_PS;

    const int tid = threadIdx.x;
    const int tx = tid & 15, ty = tid >> 4;
    const int qc = blockIdx.x, h = blockIdx.y, b = blockIdx.z;
    const int i0 = qc * 128;
    const bool has_self = (qc > 0);
    const int lane = tid & 31, wid = tid >> 5;

    const float* rpe_bh = rpe + ((size_t)(b * HH + h)) * NDIM * NDIM;

    // ---- self-dot precompute (pairs of threads per query) ----
    if (has_self) {
        const int i = tid >> 1;
        const int dh = (tid & 1) * 32;
        const float* qrow = q + ((size_t)(b * NDIM + i0 + i)) * DMODEL + h * DKH + dh;
        const float* krow = k + ((size_t)(b * NDIM + i0 + i)) * DMODEL + h * DKH + dh;
        float p = 0.f;
#pragma unroll
        for (int d = 0; d < 32; d += 4) {
            float4 q4 = *(const float4*)(qrow + d);
            float4 k4 = *(const float4*)(krow + d);
            p = fmaf(q4.x, k4.x, p);
            p = fmaf(q4.y, k4.y, p);
            p = fmaf(q4.z, k4.z, p);
            p = fmaf(q4.w, k4.w, p);
        }
        p += __shfl_xor_sync(0xffffffffu, p, 1);
        if (!(tid & 1))
            sd[i] = (p + rpe_bh[(size_t)(i0 + i) * NDIM + (i0 + i)]) * 0.125f;
    }

    // ---- load Q (transposed), K stations (transposed), V stations ----
#pragma unroll
    for (int l = 0; l < 8; l++) {
        int idx = tid + l * 256;
        int row = idx >> 4, c = idx & 15;
        float4 va = *(const float4*)(q + ((size_t)(b * NDIM + i0 + row)) * DMODEL + h * DKH + c * 4);
        Qs[(c * 4 + 0) * QS_STR + row] = va.x;
        Qs[(c * 4 + 1) * QS_STR + row] = va.y;
        Qs[(c * 4 + 2) * QS_STR + row] = va.z;
        Qs[(c * 4 + 3) * QS_STR + row] = va.w;
        float4 vk = *(const float4*)(k + ((size_t)(b * NDIM + row)) * DMODEL + h * DKH + c * 4);
        Ks[(c * 4 + 0) * QS_STR + row] = vk.x;
        Ks[(c * 4 + 1) * QS_STR + row] = vk.y;
        Ks[(c * 4 + 2) * QS_STR + row] = vk.z;
        Ks[(c * 4 + 3) * QS_STR + row] = vk.w;
        float4 vv = *(const float4*)(v + ((size_t)(b * NDIM + row)) * DMODEL + h * DKH + c * 4);
        *(float4*)(Vs + row * V_STR + c * 4) = vv;
    }
    __syncthreads();

    // ---- Phase 1: S = Q.K^T in registers, then write into aliased S ----
    {
        float acc[8][8];
#pragma unroll
        for (int i = 0; i < 8; i++)
#pragma unroll
            for (int j = 0; j < 8; j++) acc[i][j] = 0.f;

#pragma unroll 8
        for (int kk = 0; kk < DKH; kk++) {
            float a[8], bb[8];
            *(float4*)&a[0]  = *(float4*)&Qs[kk * QS_STR + ty * 4];
            *(float4*)&a[4]  = *(float4*)&Qs[kk * QS_STR + 64 + ty * 4];
            *(float4*)&bb[0] = *(float4*)&Ks[kk * QS_STR + tx * 4];
            *(float4*)&bb[4] = *(float4*)&Ks[kk * QS_STR + 64 + tx * 4];
#pragma unroll
            for (int i = 0; i < 8; i++)
#pragma unroll
                for (int j = 0; j < 8; j++)
                    acc[i][j] = fmaf(a[i], bb[j], acc[i][j]);
        }
        __syncthreads();   // Qs/Ks reads complete before S overwrite
#pragma unroll
        for (int i = 0; i < 8; i++) {
            int m = (i < 4) ? (ty * 4 + i) : (64 + ty * 4 + i - 4);
#pragma unroll
            for (int jh = 0; jh < 2; jh++) {
                int n = jh * 64 + tx * 4;
                float4 r4 = *(const float4*)(rpe_bh + (size_t)(i0 + m) * NDIM + n);
                float4 c;
                c.x = (acc[i][jh * 4 + 0] + r4.x) * 0.125f;
                c.y = (acc[i][jh * 4 + 1] + r4.y) * 0.125f;
                c.z = (acc[i][jh * 4 + 2] + r4.z) * 0.125f;
                c.w = (acc[i][jh * 4 + 3] + r4.w) * 0.125f;
                *(float4*)(S + m * S_STR + n) = c;
            }
        }
    }
    __syncthreads();

    // ---- Phase 2: row softmax (each warp handles 16 rows) ----
    for (int r16 = 0; r16 < 16; r16++) {
        int i = wid * 16 + r16;
        float4 x = *(float4*)(S + i * S_STR + lane * 4);
        float mx = fmaxf(fmaxf(x.x, x.y), fmaxf(x.z, x.w));
#pragma unroll
        for (int off = 16; off > 0; off >>= 1)
            mx = fmaxf(mx, __shfl_xor_sync(0xffffffffu, mx, off));

        float s_self = -3.0e38f;
        if (has_self) {
            s_self = sd[i];
            mx = fmaxf(mx, s_self);
        }

        float4 e;
        e.x = __expf(x.x - mx);
        e.y = __expf(x.y - mx);
        e.z = __expf(x.z - mx);
        e.w = __expf(x.w - mx);
        *(float4*)(S + i * S_STR + lane * 4) = e;
        float sum = e.x + e.y + e.z + e.w;
#pragma unroll
        for (int off = 16; off > 0; off >>= 1)
            sum += __shfl_xor_sync(0xffffffffu, sum, off);

        float pself = has_self ? __expf(s_self - mx) : 0.f;
        if (lane == 0) {
            Zr[i] = sum + pself;
            Ps[i] = pself;
        }
    }
    __syncthreads();

    // ---- Phase 3: ctx = P.V ----
    {
        float acc[8][4];
#pragma unroll
        for (int i = 0; i < 8; i++)
#pragma unroll
            for (int j = 0; j < 4; j++) acc[i][j] = 0.f;

        const int ibase = ty * 8;
#pragma unroll 4
        for (int j = 0; j < ST; j++) {
            float4 v4 = *(float4*)(Vs + j * V_STR + tx * 4);
#pragma unroll
            for (int r = 0; r < 8; r++) {
                float p = S[(ibase + r) * S_STR + j];
                acc[r][0] = fmaf(p, v4.x, acc[r][0]);
                acc[r][1] = fmaf(p, v4.y, acc[r][1]);
                acc[r][2] = fmaf(p, v4.z, acc[r][2]);
                acc[r][3] = fmaf(p, v4.w, acc[r][3]);
            }
        }

#pragma unroll
        for (int r = 0; r < 8; r++) {
            int i = ibase + r;
            float invZ = 1.f / Zr[i];
            float4 o;
            o.x = acc[r][0]; o.y = acc[r][1]; o.z = acc[r][2]; o.w = acc[r][3];
            if (has_self) {
                float ps = Ps[i];
                float4 vs = *(const float4*)(v + ((size_t)(b * NDIM + i0 + i)) * DMODEL + h * DKH + tx * 4);
                o.x = fmaf(ps, vs.x, o.x);
                o.y = fmaf(ps, vs.y, o.y);
                o.z = fmaf(ps, vs.z, o.z);
                o.w = fmaf(ps, vs.w, o.w);
            }
            o.x *= invZ; o.y *= invZ; o.z *= invZ; o.w *= invZ;
            *(float4*)(ctx + ((size_t)(b * NDIM + i0 + i)) * DMODEL + h * DKH + tx * 4) = o;
        }
    }
}

// ---------------------------------------------------------------------------
// LayerNorm over rows of 512.
// ---------------------------------------------------------------------------
__global__ __launch_bounds__(128) void ln_kernel(
    const float* __restrict__ y, const float* __restrict__ g,
    const float* __restrict__ bta, float* __restrict__ out)
{
    __shared__ float sh1[4], sh2[4];
    const int row = blockIdx.x, t = threadIdx.x;
    const int lane = t & 31, wid = t >> 5;

    float4 vv = *(const float4*)(y + (size_t)row * DMODEL + t * 4);
    float s  = vv.x + vv.y + vv.z + vv.w;
    float s2 = vv.x * vv.x + vv.y * vv.y + vv.z * vv.z + vv.w * vv.w;
#pragma unroll
    for (int off = 16; off > 0; off >>= 1) {
        s  += __shfl_xor_sync(0xffffffffu, s, off);
        s2 += __shfl_xor_sync(0xffffffffu, s2, off);
    }
    if (lane == 0) { sh1[wid] = s; sh2[wid] = s2; }
    __syncthreads();
    float tot  = sh1[0] + sh1[1] + sh1[2] + sh1[3];
    float tot2 = sh2[0] + sh2[1] + sh2[2] + sh2[3];
    float mu  = tot * (1.f / 512.f);
    float var = tot2 * (1.f / 512.f) - mu * mu;
    float rs  = rsqrtf(var + 1e-6f);

    float4 gg = *(const float4*)(g + t * 4);
    float4 bb = *(const float4*)(bta + t * 4);
    float4 o;
    o.x = (vv.x - mu) * rs * gg.x + bb.x;
    o.y = (vv.y - mu) * rs * gg.y + bb.y;
    o.z = (vv.z - mu) * rs * gg.z + bb.z;
    o.w = (vv.w - mu) * rs * gg.w + bb.w;
    *(float4*)(out + (size_t)row * DMODEL + t * 4) = o;
}

// ---------------------------------------------------------------------------
extern "C" void kernel_launch(void* const* d_in, const int* in_sizes, int n_in,
                              void* d_out, int out_size)
{
    const float* hidden = (const float*)d_in[0];
    const float* rpe    = (const float*)d_in[1];
    const float* Wq     = (const float*)d_in[2];
    const float* Wk     = (const float*)d_in[3];
    const float* Wv     = (const float*)d_in[4];
    const float* fcw    = (const float*)d_in[5];
    const float* fcb    = (const float*)d_in[6];
    const float* lng    = (const float*)d_in[7];
    const float* lnb    = (const float*)d_in[8];
    float* out = (float*)d_out;

    float *qb, *kb, *vb, *ctxb, *yb;
    __nv_bfloat16 *ahi, *alo, *chi, *clo, *whi, *wlo;
    cudaGetSymbolAddress((void**)&qb, g_q);
    cudaGetSymbolAddress((void**)&kb, g_k);
    cudaGetSymbolAddress((void**)&vb, g_v);
    cudaGetSymbolAddress((void**)&ctxb, g_ctx);
    cudaGetSymbolAddress((void**)&yb, g_y);
    cudaGetSymbolAddress((void**)&ahi, g_ahi);
    cudaGetSymbolAddress((void**)&alo, g_alo);
    cudaGetSymbolAddress((void**)&chi, g_chi);
    cudaGetSymbolAddress((void**)&clo, g_clo);
    cudaGetSymbolAddress((void**)&whi, g_whi);
    cudaGetSymbolAddress((void**)&wlo, g_wlo);

    static int attr_set = 0;
    if (!attr_set) {
        cudaFuncSetAttribute(gemm_tc, cudaFuncAttributeMaxDynamicSharedMemorySize, GEMM_SMEM);
        cudaFuncSetAttribute(attn_kernel, cudaFuncAttributeMaxDynamicSharedMemorySize, ATTN_SMEM);
        attr_set = 1;
    }

    const int n4h = MROWS * DMODEL / 4;
    const int n4w = WSZ / 4;

    split_kernel<<<n4h / 256, 256>>>(hidden, ahi, alo, n4h);
    split4_kernel<<<dim3(n4w / 256, 4), 256>>>(Wq, Wk, Wv, fcw, whi, wlo);

    // fused QKV: grid.z selects weight slab + output
    gemm_tc<<<dim3(DMODEL / 128, MROWS / 128, 3), 128, GEMM_SMEM>>>(
        ahi, alo, whi, wlo, nullptr, nullptr, qb, kb, vb);

    attn_kernel<<<dim3(NDIM / 128, HH, BDIM), 256, ATTN_SMEM>>>(qb, kb, vb, rpe, ctxb);

    split_kernel<<<n4h / 256, 256>>>(ctxb, chi, clo, n4h);
    gemm_tc<<<dim3(DMODEL / 128, MROWS / 128, 1), 128, GEMM_SMEM>>>(
        chi, clo, whi + 3 * WSZ, wlo + 3 * WSZ, fcb, hidden, yb, yb, yb);

    ln_kernel<<<MROWS, 128>>>(yb, lng, lnb, out);
}